// round 7
// baseline (speedup 1.0000x reference)
#include <cuda_runtime.h>
#include <math.h>
#include <stdint.h>

// Problem dims
#define N_PTS   32768            // B*H*W
#define K_CB    2048
#define C_DIM   64
#define B_SZ    32
#define HW      1024             // H*W

// Output offsets (tuple flattened, fp32)
#define OFF_LOSS  ((size_t)0)
#define OFF_STE   ((size_t)1)
#define OFF_PERP  ((size_t)2097153)
#define OFF_OH    ((size_t)2097154)
#define OFF_IDX   ((size_t)69206018)
#define OFF_HIST  ((size_t)69238786)

// Scratch (device globals: sanctioned alternative to cudaMalloc)
__device__ float  g_m[(size_t)N_PTS * K_CB];   // dot(z_n, c_k), 256 MB
__device__ float  g_cc[K_CB];
__device__ float  g_zz[N_PTS];
__device__ int    g_counts[K_CB];
__device__ double g_loss;

// ---------------------------------------------------------------------------
// K0: row norms (cc, zz) + zero small accumulators
// Hypothesis: reference runs on CPU XLA, where sum(x*x, axis=1) is a strictly
// SEQUENTIAL left-to-right scalar loop with separate mul and add (no FMA, no
// reassociation). Reproduce that exactly: one thread per row, loop-carried
// __fadd_rn(__fmul_rn(...)) chain over c = 0..63.
// ---------------------------------------------------------------------------
__global__ void norms_kernel(const float* __restrict__ z,
                             const float* __restrict__ cb) {
    if (blockIdx.x == 0) {
        for (int i = threadIdx.x; i < K_CB; i += blockDim.x) g_counts[i] = 0;
        if (threadIdx.x == 0) g_loss = 0.0;
    }
    int r = blockIdx.x * blockDim.x + threadIdx.x;
    if (r < K_CB) {
        const float* row = cb + (size_t)r * C_DIM;
        float s = 0.0f;
        #pragma unroll
        for (int c = 0; c < C_DIM; c++) {
            float v = row[c];
            s = __fadd_rn(s, __fmul_rn(v, v));
        }
        g_cc[r] = s;
    } else if (r < K_CB + N_PTS) {
        int n = r - K_CB;
        int b = n >> 10, p = n & 1023;
        const float* zp = z + (size_t)b * (C_DIM * HW) + p;
        float s = 0.0f;
        #pragma unroll
        for (int c = 0; c < C_DIM; c++) {
            float v = zp[(size_t)c * HW];
            s = __fadd_rn(s, __fmul_rn(v, v));
        }
        g_zz[n] = s;
    }
}

// ---------------------------------------------------------------------------
// K1: GEMM  m[n,k] = sum_c z[n,c] * cb[k,c].  128x128 tile, 256 threads, 8x8/thread.
// Sequential FMA chain over c=0..63 (single accumulator) — matches Eigen/cublas
// accumulation order (sequential k, fused multiply-add) bit-exactly.
// Dynamic smem: As[64][128] (z as [c][n]) + Bs[128][68] (cb as [k][c], padded)
// ---------------------------------------------------------------------------
#define GEMM_SMEM_FLOATS (64 * 128 + 128 * 68)
__global__ void __launch_bounds__(256) gemm_kernel(const float* __restrict__ z,
                                                   const float* __restrict__ cb) {
    extern __shared__ float smem[];
    float* As = smem;              // [c][n] stride 128
    float* Bs = smem + 64 * 128;   // [k][c] stride 68 (272B rows, 16B aligned)

    int t  = threadIdx.x;
    int n0 = blockIdx.x * 128;
    int k0 = blockIdx.y * 128;
    int b  = n0 >> 10, p0 = n0 & 1023;
    const float* zb = z + (size_t)b * (C_DIM * HW) + p0;

    #pragma unroll
    for (int i = 0; i < 8; i++) {
        int idx = t + i * 256;            // 2048 float4 of As
        int c = idx >> 5, x4 = idx & 31;
        *(float4*)&As[c * 128 + x4 * 4] = *(const float4*)(zb + (size_t)c * HW + x4 * 4);
    }
    #pragma unroll
    for (int i = 0; i < 8; i++) {
        int idx = t + i * 256;            // 2048 float4 of Bs
        int kk = idx >> 4, c4 = idx & 15;
        *(float4*)&Bs[kk * 68 + c4 * 4] = *(const float4*)(cb + (size_t)(k0 + kk) * C_DIM + c4 * 4);
    }
    __syncthreads();

    int tn = t & 15, tk = t >> 4;
    float acc[8][8];
    #pragma unroll
    for (int i = 0; i < 8; i++)
        #pragma unroll
        for (int j = 0; j < 8; j++) acc[i][j] = 0.0f;

    #pragma unroll
    for (int c = 0; c < 64; c++) {
        float a[8], bb[8];
        *(float4*)&a[0] = *(float4*)&As[c * 128 + tn * 8];
        *(float4*)&a[4] = *(float4*)&As[c * 128 + tn * 8 + 4];
        #pragma unroll
        for (int j = 0; j < 8; j++) bb[j] = Bs[(tk * 8 + j) * 68 + c];
        #pragma unroll
        for (int i = 0; i < 8; i++)
            #pragma unroll
            for (int j = 0; j < 8; j++)
                acc[i][j] = __fmaf_rn(a[i], bb[j], acc[i][j]);
    }

    float* mp = g_m + (size_t)n0 * K_CB + k0;
    #pragma unroll
    for (int i = 0; i < 8; i++) {
        float* row = mp + (size_t)(tn * 8 + i) * K_CB + tk * 8;
        *(float4*)row       = *(float4*)&acc[i][0];
        *(float4*)(row + 4) = *(float4*)&acc[i][4];
    }
}

// ---------------------------------------------------------------------------
// K2: per-point pass. Block = 64 points (same batch). 256 threads.
// distances -> argmin (first-occurrence) -> softmax -> hist, idx, onehot, ste, loss
// ---------------------------------------------------------------------------
__global__ void __launch_bounds__(256) point_kernel(const float* __restrict__ z,
                                                    const float* __restrict__ cb,
                                                    float* __restrict__ out) {
    __shared__ float cc_s[K_CB];
    __shared__ float hist_s[K_CB];
    __shared__ float s_val[256];
    __shared__ int   s_idx[256];
    __shared__ float s_sum[256];
    __shared__ int   idx_s[64];

    int t = threadIdx.x;
    for (int i = t; i < K_CB; i += 256) { cc_s[i] = g_cc[i]; hist_s[i] = 0.0f; }
    __syncthreads();

    int n_base = blockIdx.x * 64;
    int b = n_base >> 10;

    for (int p = 0; p < 64; p++) {
        int n = n_base + p;
        float zz = g_zz[n];
        const float* mrow = g_m + (size_t)n * K_CB;

        float d[8], w[8];
        float best = 3.4e38f; int bidx = 0;
        #pragma unroll
        for (int j = 0; j < 8; j++) {
            int k = t + j * 256;
            float m  = mrow[k];
            float tc = __fadd_rn(zz, cc_s[k]);          // fl(zz + cc)
            float dd = __fmaf_rn(-2.0f, m, tc);         // fl(tc - 2m) (2m exact)
            d[j] = dd;
            if (dd < best) { best = dd; bidx = k; }     // first-occurrence within thread
        }
        s_val[t] = best; s_idx[t] = bidx;
        __syncthreads();
        for (int s = 128; s > 0; s >>= 1) {
            if (t < s) {
                float v2 = s_val[t + s]; int i2 = s_idx[t + s];
                if (v2 < s_val[t] || (v2 == s_val[t] && i2 < s_idx[t])) {
                    s_val[t] = v2; s_idx[t] = i2;
                }
            }
            __syncthreads();
        }
        float dmin = s_val[0];
        int   imin = s_idx[0];

        float partS = 0.0f;
        #pragma unroll
        for (int j = 0; j < 8; j++) {
            float e = expf(dmin - d[j]);                // == exp(-d - max(-d))
            w[j] = e; partS += e;
        }
        s_sum[t] = partS;
        __syncthreads();
        for (int s = 128; s > 0; s >>= 1) {
            if (t < s) s_sum[t] += s_sum[t + s];
            __syncthreads();
        }
        float S = s_sum[0];
        #pragma unroll
        for (int j = 0; j < 8; j++) hist_s[t + j * 256] += w[j] / S;

        int p10 = n & 1023;
        if (t == 0) {
            idx_s[p] = imin;
            atomicAdd(&g_counts[imin], 1);
            out[OFF_IDX + n] = (float)imin;
            out[OFF_OH + ((size_t)b * K_CB + imin) * HW + p10] = 1.0f;
        }
        __syncthreads();
    }

    // ste + loss (coalesced over positions)
    float loss_part = 0.0f;
    int pbase = n_base & 1023;
    for (int e = t; e < 64 * 64; e += 256) {
        int c = e >> 6, pp = e & 63;
        size_t zoff = (size_t)b * (C_DIM * HW) + (size_t)c * HW + pbase + pp;
        float zv = z[zoff];
        float q  = cb[(size_t)idx_s[pp] * C_DIM + c];
        float diff = __fadd_rn(q, -zv);                 // zq - z
        out[OFF_STE + zoff] = __fadd_rn(zv, diff);      // z + (zq - z)
        loss_part = __fmaf_rn(diff, diff, loss_part);
    }

    // flush hist
    for (int i = t; i < K_CB; i += 256)
        atomicAdd(&out[OFF_HIST + (size_t)b * K_CB + i], hist_s[i]);

    // reduce loss
    s_sum[t] = loss_part;
    __syncthreads();
    for (int s = 128; s > 0; s >>= 1) {
        if (t < s) s_sum[t] += s_sum[t + s];
        __syncthreads();
    }
    if (t == 0) atomicAdd(&g_loss, (double)s_sum[0]);
}

// ---------------------------------------------------------------------------
// K3: scalars (loss, perplexity)
// ---------------------------------------------------------------------------
__global__ void finalize_kernel(float* __restrict__ out) {
    __shared__ float s_sum[256];
    int t = threadIdx.x;
    float part = 0.0f;
    for (int k = t; k < K_CB; k += 256) {
        float pb = (float)g_counts[k] * (1.0f / 32768.0f);
        part += pb * logf(pb + 1e-10f);
    }
    s_sum[t] = part;
    __syncthreads();
    for (int s = 128; s > 0; s >>= 1) {
        if (t < s) s_sum[t] += s_sum[t + s];
        __syncthreads();
    }
    if (t == 0) {
        out[OFF_PERP] = expf(-s_sum[0]);
        double mean = g_loss / 2097152.0;
        out[OFF_LOSS] = (float)(1.25 * mean);
    }
}

// ---------------------------------------------------------------------------
extern "C" void kernel_launch(void* const* d_in, const int* in_sizes, int n_in,
                              void* d_out, int out_size) {
    const float* z  = (const float*)d_in[0];
    const float* cb = (const float*)d_in[1];
    float* out = (float*)d_out;

    // zero onehot + hist regions (atomics / scatter targets)
    cudaMemsetAsync(out + OFF_OH,   0, (size_t)B_SZ * K_CB * HW * sizeof(float), 0);
    cudaMemsetAsync(out + OFF_HIST, 0, (size_t)B_SZ * K_CB * sizeof(float), 0);

    // norms + zero accumulators (one thread per row, sequential chain)
    {
        int rows = K_CB + N_PTS;
        int blocks = (rows + 255) / 256;
        norms_kernel<<<blocks, 256>>>(z, cb);
    }

    // GEMM
    {
        size_t smem = GEMM_SMEM_FLOATS * sizeof(float); // ~67 KB
        cudaFuncSetAttribute(gemm_kernel, cudaFuncAttributeMaxDynamicSharedMemorySize, (int)smem);
        dim3 grid(N_PTS / 128, K_CB / 128);
        gemm_kernel<<<grid, 256, smem>>>(z, cb);
    }

    // per-point pass
    point_kernel<<<N_PTS / 64, 256>>>(z, cb, out);

    // scalars
    finalize_kernel<<<1, 256>>>(out);
}

// round 8
// speedup vs baseline: 1.0886x; 1.0886x over previous
#include <cuda_runtime.h>
#include <math.h>
#include <stdint.h>

// Problem dims
#define N_PTS   32768            // B*H*W
#define K_CB    2048
#define C_DIM   64
#define B_SZ    32
#define HW      1024             // H*W

// Output offsets (tuple flattened, fp32)
#define OFF_LOSS  ((size_t)0)
#define OFF_STE   ((size_t)1)
#define OFF_PERP  ((size_t)2097153)
#define OFF_OH    ((size_t)2097154)
#define OFF_IDX   ((size_t)69206018)
#define OFF_HIST  ((size_t)69238786)

// Scratch (device globals: sanctioned alternative to cudaMalloc)
__device__ float  g_m[(size_t)N_PTS * K_CB];   // dot(z_n, c_k), 256 MB
__device__ float  g_cc[K_CB];
__device__ float  g_zz[N_PTS];
__device__ int    g_counts[K_CB];
__device__ double g_loss;

__device__ __forceinline__ unsigned long long pack2(float x, float y) {
    unsigned long long r;
    asm("mov.b64 %0, {%1, %2};" : "=l"(r) : "f"(x), "f"(y));
    return r;
}
__device__ __forceinline__ float2 unpack2(unsigned long long v) {
    float2 r;
    asm("mov.b64 {%0, %1}, %2;" : "=f"(r.x), "=f"(r.y) : "l"(v));
    return r;
}

// ---------------------------------------------------------------------------
// K0: row norms (cc, zz) + zero small accumulators.
// Reference is CPU XLA: sum(x*x) is a strictly sequential scalar loop with
// separate mul/add. One thread per row, loop-carried chain — bit-exact.
// ---------------------------------------------------------------------------
__global__ void norms_kernel(const float* __restrict__ z,
                             const float* __restrict__ cb) {
    if (blockIdx.x == 0) {
        for (int i = threadIdx.x; i < K_CB; i += blockDim.x) g_counts[i] = 0;
        if (threadIdx.x == 0) g_loss = 0.0;
    }
    int r = blockIdx.x * blockDim.x + threadIdx.x;
    if (r < K_CB) {
        const float* row = cb + (size_t)r * C_DIM;
        float s = 0.0f;
        #pragma unroll
        for (int c = 0; c < C_DIM; c++) {
            float v = row[c];
            s = __fadd_rn(s, __fmul_rn(v, v));
        }
        g_cc[r] = s;
    } else if (r < K_CB + N_PTS) {
        int n = r - K_CB;
        int b = n >> 10, p = n & 1023;
        const float* zp = z + (size_t)b * (C_DIM * HW) + p;
        float s = 0.0f;
        #pragma unroll
        for (int c = 0; c < C_DIM; c++) {
            float v = zp[(size_t)c * HW];
            s = __fadd_rn(s, __fmul_rn(v, v));
        }
        g_zz[n] = s;
    }
}

// ---------------------------------------------------------------------------
// K1: GEMM  m[n,k] = sum_c z[n,c]*cb[k,c] via packed fma.rn.f32x2 (FFMA2).
// 128x128 tile, 256 threads; each thread: 8 n (as 4 f32x2 pairs) x 8 k.
// Each accumulator lane keeps the sequential c=0..63 FMA chain -> bit-exact
// vs scalar FFMA (f32x2 rounds each half independently with .rn).
// smem: As[64][128] floats (z as [c][n]); Bs2[128][65] ull (cb dup (b,b)).
// ---------------------------------------------------------------------------
#define GEMM_SMEM_BYTES (64 * 128 * 4 + 128 * 65 * 8)   // 32768 + 66560 = 99328
__global__ void __launch_bounds__(256) gemm_kernel(const float* __restrict__ z,
                                                   const float* __restrict__ cb) {
    extern __shared__ unsigned char smem_raw[];
    float* As = (float*)smem_raw;                                    // [c][n] stride 128
    unsigned long long* Bs = (unsigned long long*)(smem_raw + 64 * 128 * 4); // [k][c] stride 65

    int t  = threadIdx.x;
    int n0 = blockIdx.x * 128;
    int k0 = blockIdx.y * 128;
    int b  = n0 >> 10, p0 = n0 & 1023;
    const float* zb = z + (size_t)b * (C_DIM * HW) + p0;

    #pragma unroll
    for (int i = 0; i < 8; i++) {
        int idx = t + i * 256;            // 2048 float4 of As
        int c = idx >> 5, x4 = idx & 31;
        *(float4*)&As[c * 128 + x4 * 4] = *(const float4*)(zb + (size_t)c * HW + x4 * 4);
    }
    #pragma unroll
    for (int i = 0; i < 8; i++) {
        int idx = t + i * 256;            // 2048 float4 of cb -> duplicated pairs
        int kk = idx >> 4, c4 = idx & 15;
        float4 v = *(const float4*)(cb + (size_t)(k0 + kk) * C_DIM + c4 * 4);
        unsigned long long* dst = &Bs[kk * 65 + c4 * 4];
        dst[0] = pack2(v.x, v.x);
        dst[1] = pack2(v.y, v.y);
        dst[2] = pack2(v.z, v.z);
        dst[3] = pack2(v.w, v.w);
    }
    __syncthreads();

    int tn = t & 15, tk = t >> 4;
    unsigned long long acc[4][8];
    #pragma unroll
    for (int i = 0; i < 4; i++)
        #pragma unroll
        for (int j = 0; j < 8; j++) acc[i][j] = 0ULL;

    #pragma unroll
    for (int c = 0; c < 64; c++) {
        ulonglong2 a01 = *(const ulonglong2*)&As[c * 128 + tn * 8];
        ulonglong2 a23 = *(const ulonglong2*)&As[c * 128 + tn * 8 + 4];
        unsigned long long A2[4];
        A2[0] = a01.x; A2[1] = a01.y; A2[2] = a23.x; A2[3] = a23.y;
        #pragma unroll
        for (int j = 0; j < 8; j++) {
            unsigned long long B2 = Bs[(tk * 8 + j) * 65 + c];
            #pragma unroll
            for (int i = 0; i < 4; i++)
                asm("fma.rn.f32x2 %0, %1, %2, %0;"
                    : "+l"(acc[i][j]) : "l"(A2[i]), "l"(B2));
        }
    }

    float* mp = g_m + (size_t)n0 * K_CB + k0;
    #pragma unroll
    for (int i = 0; i < 4; i++) {
        float lo[8], hi[8];
        #pragma unroll
        for (int j = 0; j < 8; j++) {
            float2 u = unpack2(acc[i][j]);
            lo[j] = u.x; hi[j] = u.y;
        }
        float* row0 = mp + (size_t)(tn * 8 + 2 * i) * K_CB + tk * 8;
        float* row1 = row0 + K_CB;
        *(float4*)row0       = *(float4*)&lo[0];
        *(float4*)(row0 + 4) = *(float4*)&lo[4];
        *(float4*)row1       = *(float4*)&hi[0];
        *(float4*)(row1 + 4) = *(float4*)&hi[4];
    }
}

// ---------------------------------------------------------------------------
// K2: per-point pass, WARP-PER-POINT (no block syncs in main loop).
// Block = 64 points (8 warps x 8 iters). Lane covers k = lane + 32j, j<64.
// Argmin bit-exact: fma(-2,m, fadd(zz,cc)), in-lane first-occurrence (k
// ascending), warp reduce with tie -> smaller index. Softmax weights via
// __expf + reciprocal-mul (feeds hist only; 1e-3 tolerance).
// Dynamic smem: cc[2048] + per-warp hist[8][2048] + idx[64].
// ---------------------------------------------------------------------------
#define POINT_SMEM_BYTES ((K_CB + 8 * K_CB + 64) * 4)   // 73984
__global__ void __launch_bounds__(256) point_kernel(const float* __restrict__ z,
                                                    const float* __restrict__ cb,
                                                    float* __restrict__ out) {
    extern __shared__ float psmem[];
    float* cc_s   = psmem;                 // [2048]
    float* hist_s = psmem + K_CB;          // [8][2048]
    int*   idx_s  = (int*)(psmem + K_CB + 8 * K_CB);  // [64]
    __shared__ float s_red[256];

    int t = threadIdx.x, wid = t >> 5, lane = t & 31;
    for (int i = t; i < K_CB; i += 256) cc_s[i] = g_cc[i];
    for (int i = t; i < 8 * K_CB; i += 256) hist_s[i] = 0.0f;
    __syncthreads();

    int n_base = blockIdx.x * 64;
    int b = n_base >> 10;
    float* hw = hist_s + wid * K_CB;

    for (int it = 0; it < 8; it++) {
        int n = n_base + it * 8 + wid;
        float zz = g_zz[n];
        const float* mrow = g_m + (size_t)n * K_CB;

        float d[64];
        float best = 3.4e38f; int bidx = 0;
        #pragma unroll
        for (int j = 0; j < 64; j++) {
            int k = lane + j * 32;
            float m  = mrow[k];
            float dd = __fmaf_rn(-2.0f, m, __fadd_rn(zz, cc_s[k]));
            d[j] = dd;
            if (dd < best) { best = dd; bidx = k; }   // first occurrence (k ascending)
        }
        #pragma unroll
        for (int o = 16; o > 0; o >>= 1) {
            float v2 = __shfl_xor_sync(0xffffffffu, best, o);
            int   i2 = __shfl_xor_sync(0xffffffffu, bidx, o);
            if (v2 < best || (v2 == best && i2 < bidx)) { best = v2; bidx = i2; }
        }
        // best = dmin, bidx = argmin (all lanes agree)
        float S = 0.0f;
        #pragma unroll
        for (int j = 0; j < 64; j++) {
            float e = __expf(best - d[j]);
            d[j] = e; S += e;
        }
        #pragma unroll
        for (int o = 16; o > 0; o >>= 1)
            S += __shfl_xor_sync(0xffffffffu, S, o);
        float Sinv = 1.0f / S;
        #pragma unroll
        for (int j = 0; j < 64; j++)
            hw[lane + j * 32] += d[j] * Sinv;

        if (lane == 0) {
            idx_s[it * 8 + wid] = bidx;
            atomicAdd(&g_counts[bidx], 1);
            out[OFF_IDX + n] = (float)bidx;
            out[OFF_OH + ((size_t)b * K_CB + bidx) * HW + (n & 1023)] = 1.0f;
        }
    }
    __syncthreads();

    // flush hist: sum the 8 per-warp copies, atomically add into out
    for (int i = t; i < K_CB; i += 256) {
        float s = hist_s[i];
        #pragma unroll
        for (int w = 1; w < 8; w++) s += hist_s[w * K_CB + i];
        atomicAdd(&out[OFF_HIST + (size_t)b * K_CB + i], s);
    }

    // ste + loss (coalesced over positions)
    float loss_part = 0.0f;
    int pbase = n_base & 1023;
    for (int e = t; e < 64 * 64; e += 256) {
        int c = e >> 6, pp = e & 63;
        size_t zoff = (size_t)b * (C_DIM * HW) + (size_t)c * HW + pbase + pp;
        float zv = z[zoff];
        float q  = cb[(size_t)idx_s[pp] * C_DIM + c];
        float diff = __fadd_rn(q, -zv);                 // zq - z
        out[OFF_STE + zoff] = __fadd_rn(zv, diff);      // z + (zq - z)
        loss_part = __fmaf_rn(diff, diff, loss_part);
    }
    s_red[t] = loss_part;
    __syncthreads();
    for (int s = 128; s > 0; s >>= 1) {
        if (t < s) s_red[t] += s_red[t + s];
        __syncthreads();
    }
    if (t == 0) atomicAdd(&g_loss, (double)s_red[0]);
}

// ---------------------------------------------------------------------------
// K3: scalars (loss, perplexity)
// ---------------------------------------------------------------------------
__global__ void finalize_kernel(float* __restrict__ out) {
    __shared__ float s_sum[256];
    int t = threadIdx.x;
    float part = 0.0f;
    for (int k = t; k < K_CB; k += 256) {
        float pb = (float)g_counts[k] * (1.0f / 32768.0f);
        part += pb * logf(pb + 1e-10f);
    }
    s_sum[t] = part;
    __syncthreads();
    for (int s = 128; s > 0; s >>= 1) {
        if (t < s) s_sum[t] += s_sum[t + s];
        __syncthreads();
    }
    if (t == 0) {
        out[OFF_PERP] = expf(-s_sum[0]);
        double mean = g_loss / 2097152.0;
        out[OFF_LOSS] = (float)(1.25 * mean);
    }
}

// ---------------------------------------------------------------------------
extern "C" void kernel_launch(void* const* d_in, const int* in_sizes, int n_in,
                              void* d_out, int out_size) {
    const float* z  = (const float*)d_in[0];
    const float* cb = (const float*)d_in[1];
    float* out = (float*)d_out;

    // zero onehot + hist regions (scatter / atomic targets)
    cudaMemsetAsync(out + OFF_OH,   0, (size_t)B_SZ * K_CB * HW * sizeof(float), 0);
    cudaMemsetAsync(out + OFF_HIST, 0, (size_t)B_SZ * K_CB * sizeof(float), 0);

    // norms + zero accumulators (one thread per row, sequential chain)
    {
        int rows = K_CB + N_PTS;
        int blocks = (rows + 255) / 256;
        norms_kernel<<<blocks, 256>>>(z, cb);
    }

    // GEMM (FFMA2)
    {
        cudaFuncSetAttribute(gemm_kernel, cudaFuncAttributeMaxDynamicSharedMemorySize,
                             GEMM_SMEM_BYTES);
        dim3 grid(N_PTS / 128, K_CB / 128);
        gemm_kernel<<<grid, 256, GEMM_SMEM_BYTES>>>(z, cb);
    }

    // per-point pass (warp-per-point)
    {
        cudaFuncSetAttribute(point_kernel, cudaFuncAttributeMaxDynamicSharedMemorySize,
                             POINT_SMEM_BYTES);
        point_kernel<<<N_PTS / 64, 256, POINT_SMEM_BYTES>>>(z, cb, out);
    }

    // scalars
    finalize_kernel<<<1, 256>>>(out);
}